// round 15
// baseline (speedup 1.0000x reference)
#include <cuda_runtime.h>
#include <cuda_bf16.h>

// ---------------------------------------------------------------------------
// SPLoss: fused CE + quantile-threshold reweighted mean
//   ce[i]   = logsumexp(output[i,:]) - output[i, target[i]]
//   lambda  = k-th smallest ce, k = int(B * N_ratio(epoch))
//   v       = (1 - ce/lambda)^(1/(q_t-1)),  0 where ce >= lambda, capped at 10
//   out     = mean(ce * v)
// ---------------------------------------------------------------------------

#define B_MAX 32768
#define C_DIM 1000
#define C_VEC4 250   // 1000/4

__device__ float g_ce[B_MAX];
__device__ int   g_tgt_is64;

// -------- Kernel 0: detect target dtype (int32 vs int64-LE), in-bounds -----
// Reads only int32 words at indices < B (valid for BOTH layouts). For int64-LE
// with values in [0,1000), every odd word is a zero high-word; for int32,
// odd words are random labels and some are nonzero (P(all zero) ~ 0).
__global__ void detect_tgt_kernel(const int* __restrict__ tgt32, int B)
{
    __shared__ int s_or;
    if (threadIdx.x == 0) s_or = 0;
    __syncthreads();
    int acc = 0;
    for (int i = 2 * threadIdx.x + 1; i < B; i += 2 * blockDim.x)
        acc |= tgt32[i];
    if (acc) atomicOr(&s_or, 1);
    __syncthreads();
    if (threadIdx.x == 0) g_tgt_is64 = (s_or == 0) ? 1 : 0;
}

// ---------------- Kernel 1: per-row cross-entropy (1 warp per row) ---------
__global__ void __launch_bounds__(256) ce_kernel(
    const float* __restrict__ out,
    const void* __restrict__ tgt,
    int B)
{
    int warp = (blockIdx.x * blockDim.x + threadIdx.x) >> 5;
    int lane = threadIdx.x & 31;
    if (warp >= B) return;

    const float4* row = reinterpret_cast<const float4*>(out + (size_t)warp * C_DIM);

    const float NEG = -1e30f;
    float4 f[8];
    // Single coalesced read of the whole row, held in registers.
    #pragma unroll
    for (int i = 0; i < 8; i++) {
        int idx = lane + i * 32;
        if (idx < C_VEC4) f[i] = row[idx];
        else              f[i] = make_float4(NEG, NEG, NEG, NEG);
    }

    // Pass 1 (registers): max
    float m = NEG;
    #pragma unroll
    for (int i = 0; i < 8; i++)
        m = fmaxf(m, fmaxf(fmaxf(f[i].x, f[i].y), fmaxf(f[i].z, f[i].w)));
    #pragma unroll
    for (int o = 16; o > 0; o >>= 1)
        m = fmaxf(m, __shfl_xor_sync(0xffffffffu, m, o));

    // Pass 2 (registers): sum of exp(x - m). exp(NEG - m) underflows to 0.
    float s = 0.0f;
    #pragma unroll
    for (int i = 0; i < 8; i++) {
        s += __expf(f[i].x - m);
        s += __expf(f[i].y - m);
        s += __expf(f[i].z - m);
        s += __expf(f[i].w - m);
    }
    #pragma unroll
    for (int o = 16; o > 0; o >>= 1)
        s += __shfl_xor_sync(0xffffffffu, s, o);

    if (lane == 0) {
        int t;
        if (g_tgt_is64) t = (int)((const long long*)tgt)[warp];
        else            t = ((const int*)tgt)[warp];
        // defensive clamp: never fault even on mis-detect
        t = max(0, min(t, C_DIM - 1));
        float xt = out[(size_t)warp * C_DIM + t];
        g_ce[warp] = __logf(s) + m - xt;   // logsumexp - x_target
    }
}

// ------------- Kernel 2: radix-select lambda + weighted mean (1 block) -----
__device__ __forceinline__ unsigned map_key(float x) {
    unsigned u = __float_as_uint(x);
    // Monotone map: order of mapped uints == order of floats
    return (u & 0x80000000u) ? ~u : (u | 0x80000000u);
}

__global__ void __launch_bounds__(1024) select_reduce_kernel(
    const int* __restrict__ epoch_ptr,
    float* __restrict__ result,
    int B)
{
    __shared__ unsigned s_hist[256];
    __shared__ unsigned s_prefix;
    __shared__ unsigned s_mask;
    __shared__ int      s_k;
    __shared__ float    s_red[32];

    int tid = threadIdx.x;

    // --- schedule (epoch read as int32 low word; valid for LE int32/int64) ---
    int epoch = *epoch_ptr;
    float ratio; int q;
    if      (epoch <= 25) { ratio = 0.7f; q = 2; }
    else if (epoch <= 75) { ratio = 0.8f; q = 0; }
    else if (epoch <= 95) { ratio = 0.9f; q = 0; }
    else                  { ratio = 1.0f; q = 0; }
    float exponent = 1.0f / (float)(q - 1);

    int k = (int)((double)B * (double)ratio);   // matches python int(B*ratio)
    if (k > B - 1) k = B - 1;                   // JAX clamps OOB gather

    if (tid == 0) { s_prefix = 0; s_mask = 0; s_k = k; }
    __syncthreads();

    // --- 4-pass MSB radix select: exact k-th smallest (bit-identical) ---
    #pragma unroll
    for (int shift = 24; shift >= 0; shift -= 8) {
        if (tid < 256) s_hist[tid] = 0;
        __syncthreads();

        unsigned prefix = s_prefix, mask = s_mask;
        for (int i = tid; i < B; i += 1024) {
            unsigned u = map_key(g_ce[i]);
            if ((u & mask) == prefix)
                atomicAdd(&s_hist[(u >> shift) & 255u], 1u);
        }
        __syncthreads();

        if (tid == 0) {
            unsigned kk = (unsigned)s_k;
            unsigned cum = 0;
            int d = 0;
            for (; d < 256; d++) {
                unsigned c = s_hist[d];
                if (kk < cum + c) break;
                cum += c;
            }
            s_k      = (int)(kk - cum);
            s_prefix = prefix | ((unsigned)d << shift);
            s_mask   = mask | (0xFFu << shift);
        }
        __syncthreads();
    }

    unsigned lu = s_prefix;
    float lambda = (lu & 0x80000000u) ? __uint_as_float(lu ^ 0x80000000u)
                                      : __uint_as_float(~lu);
    float inv_lambda = 1.0f / lambda;

    // --- weighted mean reduction ---
    float acc = 0.0f;
    for (int i = tid; i < B; i += 1024) {
        float ce = g_ce[i];
        float v;
        if (ce >= lambda) {
            v = 0.0f;
        } else {
            float base = 1.0f - ce * inv_lambda;     // > 0 here
            v = (exponent == 1.0f) ? base : __powf(base, exponent);
            if (v >= 10.0f) v = 10.0f;
        }
        acc += ce * v;
    }

    // block reduce: warp shuffle + shared
    int lane = tid & 31, wid = tid >> 5;
    #pragma unroll
    for (int o = 16; o > 0; o >>= 1)
        acc += __shfl_xor_sync(0xffffffffu, acc, o);
    if (lane == 0) s_red[wid] = acc;
    __syncthreads();
    if (tid < 32) {
        acc = s_red[tid];
        #pragma unroll
        for (int o = 16; o > 0; o >>= 1)
            acc += __shfl_xor_sync(0xffffffffu, acc, o);
        if (tid == 0) result[0] = acc / (float)B;
    }
}

// ---------------------------------------------------------------------------
extern "C" void kernel_launch(void* const* d_in, const int* in_sizes, int n_in,
                              void* d_out, int out_size)
{
    // Identify inputs by element count, not position:
    //   output: B*C (huge), epoch: 1, target: B (the remaining one)
    int io = -1, it = -1, ie = -1;
    for (int i = 0; i < n_in; i++) {
        if (in_sizes[i] > 1000000)      io = i;
        else if (in_sizes[i] == 1)      ie = i;
        else                            it = i;
    }
    const float* output = (const float*)d_in[io];
    const void*  target = d_in[it];
    const int*   epoch  = (const int*)d_in[ie];

    int B = in_sizes[it];
    if (B > B_MAX) B = B_MAX;

    int threads = 256;
    int blocks = (B * 32 + threads - 1) / threads;   // 1 warp per row

    detect_tgt_kernel<<<1, 256>>>((const int*)target, B);
    ce_kernel<<<blocks, threads>>>(output, target, B);
    select_reduce_kernel<<<1, 1024>>>(epoch, (float*)d_out, B);
}